// round 1
// baseline (speedup 1.0000x reference)
#include <cuda_runtime.h>
#include <math.h>

#define NN 4096
#define MAXN 256
#define NGRAPH 64

// ---------------- scratch (device globals; no allocation) ----------------
__device__ float g_f[NN * 64];          // per-layer linear features (both heads)
__device__ float g_xbuf[2][NN * 64];    // layer outputs (ping-pong)
__device__ float g_h[NN * 192];         // concat(x1,x2,x3)
__device__ int   g_col[NN * MAXN];      // padded CSR columns
__device__ int   g_cnt[NN];             // row neighbor counts
__device__ float g_s1[2 * NN];          // attention src scores per head
__device__ float g_s2[2 * NN];          // attention dst scores per head
__device__ float g_pool[NGRAPH * 192];  // pooled graph features

// ---------------- CSR build (deterministic via ballot ordering) ----------
__global__ void build_csr(const float* __restrict__ adj) {
    int warp = (blockIdx.x * blockDim.x + threadIdx.x) >> 5;
    int lane = threadIdx.x & 31;
    if (warp >= NN) return;
    const float* row = adj + (size_t)warp * NN;
    int base = 0;
    for (int c0 = 0; c0 < NN; c0 += 32) {
        float v = row[c0 + lane];
        unsigned m = __ballot_sync(0xffffffffu, v > 0.0f);
        if (v > 0.0f) {
            int pos = base + __popc(m & ((1u << lane) - 1u));
            if (pos < MAXN) g_col[warp * MAXN + pos] = c0 + lane;
        }
        base += __popc(m);
    }
    if (lane == 0) g_cnt[warp] = base < MAXN ? base : MAXN;
}

// ---------------- f = x @ Wcat + bcat  (BM=32, BN=64, BK=32) -------------
// W layout: [2, in, 32] ; output col j -> head j/32, unit j%32. b: [2,32].
__global__ void gemm_f(const float* __restrict__ xext, int sel, int in,
                       const float* __restrict__ W, const float* __restrict__ b) {
    const float* __restrict__ x = (sel < 0) ? xext : g_xbuf[sel];
    __shared__ float As[32][32];  // [kk][row]
    __shared__ float Ws[32][64];  // [kk][col]
    int row0 = blockIdx.x * 32;
    int tid = threadIdx.x;
    int tc = tid & 15;   // col group -> cols 4*tc..4*tc+3
    int tr = tid >> 4;   // row group -> rows 2*tr..2*tr+1
    float acc[2][4] = {{0.f, 0.f, 0.f, 0.f}, {0.f, 0.f, 0.f, 0.f}};

    for (int kb = 0; kb < in; kb += 32) {
#pragma unroll
        for (int i = 0; i < 4; i++) {
            int idx = tid + i * 256;
            int kk = idx & 31, rl = idx >> 5;
            As[kk][rl] = x[(size_t)(row0 + rl) * in + kb + kk];
        }
#pragma unroll
        for (int i = 0; i < 8; i++) {
            int idx = tid + i * 256;
            int col = idx & 63, kk = idx >> 6;
            int kh = col >> 5, h = col & 31;
            Ws[kk][col] = W[((size_t)kh * in + kb + kk) * 32 + h];
        }
        __syncthreads();
#pragma unroll
        for (int kk = 0; kk < 32; kk++) {
            float a0 = As[kk][2 * tr];
            float a1 = As[kk][2 * tr + 1];
            float w0 = Ws[kk][4 * tc + 0];
            float w1 = Ws[kk][4 * tc + 1];
            float w2 = Ws[kk][4 * tc + 2];
            float w3 = Ws[kk][4 * tc + 3];
            acc[0][0] = fmaf(a0, w0, acc[0][0]);
            acc[0][1] = fmaf(a0, w1, acc[0][1]);
            acc[0][2] = fmaf(a0, w2, acc[0][2]);
            acc[0][3] = fmaf(a0, w3, acc[0][3]);
            acc[1][0] = fmaf(a1, w0, acc[1][0]);
            acc[1][1] = fmaf(a1, w1, acc[1][1]);
            acc[1][2] = fmaf(a1, w2, acc[1][2]);
            acc[1][3] = fmaf(a1, w3, acc[1][3]);
        }
        __syncthreads();
    }
#pragma unroll
    for (int r = 0; r < 2; r++) {
#pragma unroll
        for (int c = 0; c < 4; c++) {
            int col = 4 * tc + c;
            g_f[(size_t)(row0 + 2 * tr + r) * 64 + col] = acc[r][c] + b[col];
        }
    }
}

// ---------------- s1/s2 attention scores (one warp per row) --------------
__global__ void attn_scores(const float* __restrict__ a1w, const float* __restrict__ a1b,
                            const float* __restrict__ a2w, const float* __restrict__ a2b) {
    int warp = (blockIdx.x * blockDim.x + threadIdx.x) >> 5;
    int lane = threadIdx.x & 31;
    if (warp >= NN) return;
    float f0 = g_f[warp * 64 + lane];
    float f1 = g_f[warp * 64 + 32 + lane];
    float p10 = f0 * a1w[lane];
    float p11 = f1 * a1w[32 + lane];
    float p20 = f0 * a2w[lane];
    float p21 = f1 * a2w[32 + lane];
#pragma unroll
    for (int o = 16; o; o >>= 1) {
        p10 += __shfl_down_sync(0xffffffffu, p10, o);
        p11 += __shfl_down_sync(0xffffffffu, p11, o);
        p20 += __shfl_down_sync(0xffffffffu, p20, o);
        p21 += __shfl_down_sync(0xffffffffu, p21, o);
    }
    if (lane == 0) {
        g_s1[warp] = p10 + a1b[0];
        g_s1[NN + warp] = p11 + a1b[1];
        g_s2[warp] = p20 + a2b[0];
        g_s2[NN + warp] = p21 + a2b[1];
    }
}

// ---------------- sparse softmax-attention aggregation -------------------
// 128 threads per row. Exact: masked entries softmax to 0, so only CSR
// neighbors contribute.
__global__ void aggregate(int outsel, int hoff) {
    int i = blockIdx.x;
    int t = threadIdx.x;
    __shared__ int   cols[MAXN];
    __shared__ float lg[2][MAXN];
    __shared__ float redm[2][4];
    __shared__ float reds[2][4];

    int cnt = g_cnt[i];
    float s10 = g_s1[i], s11 = g_s1[NN + i];

    float m0 = -1e30f, m1 = -1e30f;
    for (int n = t; n < cnt; n += 128) {
        int j = g_col[i * MAXN + n];
        cols[n] = j;
        float e0 = s10 + g_s2[j];
        float e1 = s11 + g_s2[NN + j];
        e0 = e0 > 0.f ? e0 : 0.01f * e0;   // leaky_relu 0.01
        e1 = e1 > 0.f ? e1 : 0.01f * e1;
        lg[0][n] = e0;
        lg[1][n] = e1;
        m0 = fmaxf(m0, e0);
        m1 = fmaxf(m1, e1);
    }
#pragma unroll
    for (int o = 16; o; o >>= 1) {
        m0 = fmaxf(m0, __shfl_down_sync(0xffffffffu, m0, o));
        m1 = fmaxf(m1, __shfl_down_sync(0xffffffffu, m1, o));
    }
    int w = t >> 5;
    if ((t & 31) == 0) { redm[0][w] = m0; redm[1][w] = m1; }
    __syncthreads();
    float bm0 = fmaxf(fmaxf(redm[0][0], redm[0][1]), fmaxf(redm[0][2], redm[0][3]));
    float bm1 = fmaxf(fmaxf(redm[1][0], redm[1][1]), fmaxf(redm[1][2], redm[1][3]));

    float sum0 = 0.f, sum1 = 0.f;
    for (int n = t; n < cnt; n += 128) {
        float w0 = __expf(lg[0][n] - bm0);
        float w1 = __expf(lg[1][n] - bm1);
        lg[0][n] = w0;
        lg[1][n] = w1;
        sum0 += w0;
        sum1 += w1;
    }
#pragma unroll
    for (int o = 16; o; o >>= 1) {
        sum0 += __shfl_down_sync(0xffffffffu, sum0, o);
        sum1 += __shfl_down_sync(0xffffffffu, sum1, o);
    }
    if ((t & 31) == 0) { reds[0][w] = sum0; reds[1][w] = sum1; }
    __syncthreads();

    if (t < 64) {
        int k = t >> 5;
        float denom = reds[k][0] + reds[k][1] + reds[k][2] + reds[k][3];
        float inv = 1.0f / denom;
        const float* lw = lg[k];
        float acc = 0.f;
#pragma unroll 4
        for (int n = 0; n < cnt; n++) {
            acc = fmaf(lw[n], g_f[(size_t)cols[n] * 64 + t], acc);
        }
        float o = acc * inv;
        o = o > 0.f ? o : 0.f;  // relu
        g_xbuf[outsel][i * 64 + t] = o;
        g_h[i * 192 + hoff + t] = o;
    }
}

// ---------------- segment mean pool (batch is sorted) --------------------
__global__ void pool(const int* __restrict__ batch) {
    int g = blockIdx.x;   // 64 blocks
    int t = threadIdx.x;  // 192 threads
    __shared__ int sst, sen;
    if (t == 0) {
        int lo = 0, hi = NN;
        while (lo < hi) { int mid = (lo + hi) >> 1; if (batch[mid] < g) lo = mid + 1; else hi = mid; }
        sst = lo;
        hi = NN;
        while (lo < hi) { int mid = (lo + hi) >> 1; if (batch[mid] < g + 1) lo = mid + 1; else hi = mid; }
        sen = lo;
    }
    __syncthreads();
    float s = 0.f;
    for (int r = sst; r < sen; r++) s += g_h[(size_t)r * 192 + t];
    float c = (float)(sen - sst);
    g_pool[g * 192 + t] = s / fmaxf(c, 1.0f);
}

// ---------------- classifier head + softmax ------------------------------
__global__ void head(const float* __restrict__ Wf, const float* __restrict__ bf,
                     float* __restrict__ out) {
    int g = blockIdx.x;       // 64
    int lane = threadIdx.x;   // 32
    float logit = 0.f;
    float v = -1e30f;
    if (lane < 10) {
        float acc = bf[lane];
        for (int c = 0; c < 192; c++) acc = fmaf(g_pool[g * 192 + c], Wf[c * 10 + lane], acc);
        logit = acc;
        v = acc;
    }
#pragma unroll
    for (int o = 16; o; o >>= 1) v = fmaxf(v, __shfl_xor_sync(0xffffffffu, v, o));
    float e = (lane < 10) ? __expf(logit - v) : 0.f;
    float s = e;
#pragma unroll
    for (int o = 16; o; o >>= 1) s += __shfl_xor_sync(0xffffffffu, s, o);
    if (lane < 10) out[g * 10 + lane] = e / s;
}

// ---------------- launch --------------------------------------------------
extern "C" void kernel_launch(void* const* d_in, const int* in_sizes, int n_in,
                              void* d_out, int out_size) {
    const float* x     = (const float*)d_in[0];
    const float* adj   = (const float*)d_in[1];
    const int*   batch = (const int*)d_in[2];
    const float* W[3]   = {(const float*)d_in[3],  (const float*)d_in[9],  (const float*)d_in[15]};
    const float* b[3]   = {(const float*)d_in[4],  (const float*)d_in[10], (const float*)d_in[16]};
    const float* a1w[3] = {(const float*)d_in[5],  (const float*)d_in[11], (const float*)d_in[17]};
    const float* a1b[3] = {(const float*)d_in[6],  (const float*)d_in[12], (const float*)d_in[18]};
    const float* a2w[3] = {(const float*)d_in[7],  (const float*)d_in[13], (const float*)d_in[19]};
    const float* a2b[3] = {(const float*)d_in[8],  (const float*)d_in[14], (const float*)d_in[20]};
    const float* Wf = (const float*)d_in[21];
    const float* bf = (const float*)d_in[22];
    float* out = (float*)d_out;

    build_csr<<<NN / 8, 256>>>(adj);

    // layer 1: x (in=512) -> g_xbuf[0]
    gemm_f<<<NN / 32, 256>>>(x, -1, 512, W[0], b[0]);
    attn_scores<<<NN / 8, 256>>>(a1w[0], a1b[0], a2w[0], a2b[0]);
    aggregate<<<NN, 128>>>(0, 0);

    // layer 2: g_xbuf[0] (in=64) -> g_xbuf[1]
    gemm_f<<<NN / 32, 256>>>(nullptr, 0, 64, W[1], b[1]);
    attn_scores<<<NN / 8, 256>>>(a1w[1], a1b[1], a2w[1], a2b[1]);
    aggregate<<<NN, 128>>>(1, 64);

    // layer 3: g_xbuf[1] (in=64) -> g_xbuf[0] (unused afterward; h gets the data)
    gemm_f<<<NN / 32, 256>>>(nullptr, 1, 64, W[2], b[2]);
    attn_scores<<<NN / 8, 256>>>(a1w[2], a1b[2], a2w[2], a2b[2]);
    aggregate<<<NN, 128>>>(0, 128);

    pool<<<NGRAPH, 192>>>(batch);
    head<<<NGRAPH, 32>>>(Wf, bf, out);
}

// round 2
// speedup vs baseline: 1.2020x; 1.2020x over previous
#include <cuda_runtime.h>
#include <math.h>

#define NN 4096
#define MAXN 256
#define MAXNP 264   // padded for bank-conflict-free wgt[2][.]
#define NGRAPH 64

// ---------------- scratch (device globals; no allocation) ----------------
__device__ float g_f[NN * 64];          // per-layer linear features (both heads)
__device__ float g_xbuf[2][NN * 64];    // layer outputs (ping-pong)
__device__ float g_h[NN * 192];         // concat(x1,x2,x3)
__device__ int   g_col[NN * MAXN];      // padded CSR columns
__device__ int   g_cnt[NN];             // row neighbor counts
__device__ float g_s1[2 * NN];          // attention src scores per head (k*NN+row)
__device__ float g_s2[2 * NN];          // attention dst scores per head

// ---------------- GEMM f = x@Wcat + b, with fused attention scores -------
// BM=32, BN=64, BK=32, 256 threads. W layout [2][in][32], b [2][32]=[64].
// Epilogue: writes g_f and per-row per-head s1/s2 (dot with a1w/a2w + bias).
__device__ __forceinline__ void gemm_attn(
    const float* __restrict__ x, int in,
    const float* __restrict__ W, const float* __restrict__ b,
    const float* __restrict__ a1w, const float* __restrict__ a1b,
    const float* __restrict__ a2w, const float* __restrict__ a2b,
    int bid)
{
    __shared__ float As[32][33];   // [kk][row]
    __shared__ float Ws[32][64];   // [kk][col]
    int row0 = bid * 32;
    int t  = threadIdx.x;
    int tc = t & 15;               // col group: cols 4tc..4tc+3 (one head)
    int tr = t >> 4;               // row group: rows 2tr, 2tr+1
    int lr = t >> 3;               // load row 0..31
    int lc = t & 7;                // load k-group (float4)
    float acc[2][4] = {{0.f,0.f,0.f,0.f},{0.f,0.f,0.f,0.f}};

    for (int kb = 0; kb < in; kb += 32) {
        float4 xv = *(const float4*)&x[(size_t)(row0 + lr) * in + kb + 4 * lc];
        As[4*lc+0][lr] = xv.x; As[4*lc+1][lr] = xv.y;
        As[4*lc+2][lr] = xv.z; As[4*lc+3][lr] = xv.w;
#pragma unroll
        for (int j = 0; j < 2; j++) {
            int u  = t + j * 256;
            int kk = u >> 4, q = u & 15;
            int kh = q >> 3, h = (4 * q) & 31;
            float4 wv = *(const float4*)&W[((size_t)kh * in + kb + kk) * 32 + h];
            *(float4*)&Ws[kk][4 * q] = wv;
        }
        __syncthreads();
#pragma unroll
        for (int kk = 0; kk < 32; kk++) {
            float a0 = As[kk][2*tr], a1 = As[kk][2*tr+1];
            float4 wv = *(float4*)&Ws[kk][4*tc];
            acc[0][0] = fmaf(a0, wv.x, acc[0][0]);
            acc[0][1] = fmaf(a0, wv.y, acc[0][1]);
            acc[0][2] = fmaf(a0, wv.z, acc[0][2]);
            acc[0][3] = fmaf(a0, wv.w, acc[0][3]);
            acc[1][0] = fmaf(a1, wv.x, acc[1][0]);
            acc[1][1] = fmaf(a1, wv.y, acc[1][1]);
            acc[1][2] = fmaf(a1, wv.z, acc[1][2]);
            acc[1][3] = fmaf(a1, wv.w, acc[1][3]);
        }
        __syncthreads();
    }

    // epilogue: bias, store f (float4), fused attention score partials
    int col = 4 * tc;
    float b0 = b[col], b1 = b[col+1], b2 = b[col+2], b3 = b[col+3];
    float w10 = a1w[col], w11 = a1w[col+1], w12 = a1w[col+2], w13 = a1w[col+3];
    float w20 = a2w[col], w21 = a2w[col+1], w22 = a2w[col+2], w23 = a2w[col+3];
    float p1[2], p2[2];
#pragma unroll
    for (int r = 0; r < 2; r++) {
        float f0 = acc[r][0]+b0, f1 = acc[r][1]+b1, f2 = acc[r][2]+b2, f3 = acc[r][3]+b3;
        int row = row0 + 2*tr + r;
        float4 fv = {f0, f1, f2, f3};
        *(float4*)&g_f[(size_t)row * 64 + col] = fv;
        p1[r] = f0*w10 + f1*w11 + f2*w12 + f3*w13;
        p2[r] = f0*w20 + f1*w21 + f2*w22 + f3*w23;
    }
    // reduce over the 8 tc-threads of each head (width-8 groups)
#pragma unroll
    for (int o = 4; o; o >>= 1) {
        p1[0] += __shfl_down_sync(0xffffffffu, p1[0], o, 8);
        p1[1] += __shfl_down_sync(0xffffffffu, p1[1], o, 8);
        p2[0] += __shfl_down_sync(0xffffffffu, p2[0], o, 8);
        p2[1] += __shfl_down_sync(0xffffffffu, p2[1], o, 8);
    }
    if ((tc & 7) == 0) {
        int k = tc >> 3;   // head
#pragma unroll
        for (int r = 0; r < 2; r++) {
            int row = row0 + 2*tr + r;
            g_s1[k * NN + row] = p1[r] + a1b[k];
            g_s2[k * NN + row] = p2[r] + a2b[k];
        }
    }
}

// ---------------- CSR build (float4; order within row is k-interleaved) --
__device__ __forceinline__ void csr_body(const float* __restrict__ adj, int wrow) {
    int lane = threadIdx.x & 31;
    const float4* row = (const float4*)(adj + (size_t)wrow * NN);
    int* mycol = g_col + (size_t)wrow * MAXN;
    int base = 0;
#pragma unroll 2
    for (int it = 0; it < 32; it++) {
        float4 v = row[it * 32 + lane];
        int c0 = it * 128 + 4 * lane;
        unsigned lm = (1u << lane) - 1u;
        unsigned m0 = __ballot_sync(0xffffffffu, v.x > 0.0f);
        if (v.x > 0.0f) { int p = base + __popc(m0 & lm); if (p < MAXN) mycol[p] = c0; }
        base += __popc(m0);
        unsigned m1 = __ballot_sync(0xffffffffu, v.y > 0.0f);
        if (v.y > 0.0f) { int p = base + __popc(m1 & lm); if (p < MAXN) mycol[p] = c0 + 1; }
        base += __popc(m1);
        unsigned m2 = __ballot_sync(0xffffffffu, v.z > 0.0f);
        if (v.z > 0.0f) { int p = base + __popc(m2 & lm); if (p < MAXN) mycol[p] = c0 + 2; }
        base += __popc(m2);
        unsigned m3 = __ballot_sync(0xffffffffu, v.w > 0.0f);
        if (v.w > 0.0f) { int p = base + __popc(m3 & lm); if (p < MAXN) mycol[p] = c0 + 3; }
        base += __popc(m3);
    }
    if (lane == 0) g_cnt[wrow] = base < MAXN ? base : MAXN;
}

// ---------------- fused: CSR build + layer-1 GEMM (overlap HBM & FMA) ----
__global__ void fused_csr_gemm1(
    const float* __restrict__ x, const float* __restrict__ adj,
    const float* __restrict__ W, const float* __restrict__ b,
    const float* __restrict__ a1w, const float* __restrict__ a1b,
    const float* __restrict__ a2w, const float* __restrict__ a2b)
{
    if (blockIdx.x < 128) {
        gemm_attn(x, 512, W, b, a1w, a1b, a2w, a2b, blockIdx.x);
    } else {
        int wrow = (blockIdx.x - 128) * 8 + (threadIdx.x >> 5);
        csr_body(adj, wrow);
    }
}

// ---------------- GEMM kernel for layers 2/3 -----------------------------
__global__ void gemm_k(int sel,
    const float* __restrict__ W, const float* __restrict__ b,
    const float* __restrict__ a1w, const float* __restrict__ a1b,
    const float* __restrict__ a2w, const float* __restrict__ a2b)
{
    gemm_attn(g_xbuf[sel], 64, W, b, a1w, a1b, a2w, a2b, blockIdx.x);
}

// ---------------- sparse softmax-attention aggregation -------------------
// 256 threads / row. 16 groups x 16 threads; group g handles neighbors
// n = g, g+16, ...; each thread float4-gathers 4 of the 64 features.
__global__ void aggregate(int outsel, int hoff) {
    int i = blockIdx.x;
    int t = threadIdx.x;
    __shared__ int   cols[MAXN];
    __shared__ float wgt[2][MAXNP];
    __shared__ float racc[16][64];
    __shared__ float rm[2][8], rs[2][8];

    int cnt = g_cnt[i];
    float s10 = g_s1[i], s11 = g_s1[NN + i];

    // phase 1: logits + max
    float m0 = -1e30f, m1 = -1e30f;
    for (int n = t; n < cnt; n += 256) {
        int j = g_col[(size_t)i * MAXN + n];
        cols[n] = j;
        float e0 = s10 + g_s2[j];
        float e1 = s11 + g_s2[NN + j];
        e0 = e0 > 0.f ? e0 : 0.01f * e0;
        e1 = e1 > 0.f ? e1 : 0.01f * e1;
        wgt[0][n] = e0; wgt[1][n] = e1;
        m0 = fmaxf(m0, e0); m1 = fmaxf(m1, e1);
    }
#pragma unroll
    for (int o = 16; o; o >>= 1) {
        m0 = fmaxf(m0, __shfl_down_sync(0xffffffffu, m0, o));
        m1 = fmaxf(m1, __shfl_down_sync(0xffffffffu, m1, o));
    }
    int w = t >> 5;
    if ((t & 31) == 0) { rm[0][w] = m0; rm[1][w] = m1; }
    __syncthreads();
    float bm0 = rm[0][0], bm1 = rm[1][0];
#pragma unroll
    for (int k = 1; k < 8; k++) { bm0 = fmaxf(bm0, rm[0][k]); bm1 = fmaxf(bm1, rm[1][k]); }

    // phase 2: exp + sum
    float sum0 = 0.f, sum1 = 0.f;
    for (int n = t; n < cnt; n += 256) {
        float w0 = __expf(wgt[0][n] - bm0);
        float w1 = __expf(wgt[1][n] - bm1);
        wgt[0][n] = w0; wgt[1][n] = w1;
        sum0 += w0; sum1 += w1;
    }
#pragma unroll
    for (int o = 16; o; o >>= 1) {
        sum0 += __shfl_down_sync(0xffffffffu, sum0, o);
        sum1 += __shfl_down_sync(0xffffffffu, sum1, o);
    }
    if ((t & 31) == 0) { rs[0][w] = sum0; rs[1][w] = sum1; }
    __syncthreads();

    // phase 3: weighted gather-sum, 16 neighbor-groups in parallel
    int g  = t >> 4;      // 0..15  neighbor group
    int tc = t & 15;      // 0..15  feature quad
    int k  = tc >> 3;     // head of this quad
    float a0 = 0.f, a1 = 0.f, a2 = 0.f, a3 = 0.f;
    for (int n = g; n < cnt; n += 16) {
        int j = cols[n];
        float wv = wgt[k][n];
        float4 fv = *(const float4*)&g_f[(size_t)j * 64 + 4 * tc];
        a0 = fmaf(wv, fv.x, a0);
        a1 = fmaf(wv, fv.y, a1);
        a2 = fmaf(wv, fv.z, a2);
        a3 = fmaf(wv, fv.w, a3);
    }
    float4 av = {a0, a1, a2, a3};
    *(float4*)&racc[g][4 * tc] = av;
    __syncthreads();

    // final: reduce 16 groups, normalize, relu, store
    if (t < 64) {
        int kh = t >> 5;
        float denom = 0.f;
#pragma unroll
        for (int q = 0; q < 8; q++) denom += rs[kh][q];
        float inv = 1.0f / denom;
        float s = 0.f;
#pragma unroll
        for (int q = 0; q < 16; q++) s += racc[q][t];
        float o = s * inv;
        o = o > 0.f ? o : 0.f;
        g_xbuf[outsel][(size_t)i * 64 + t] = o;
        g_h[(size_t)i * 192 + hoff + t] = o;
    }
}

// ---------------- fused segment-mean pool + classifier head --------------
__global__ void pool_head(const int* __restrict__ batch,
                          const float* __restrict__ Wf, const float* __restrict__ bf,
                          float* __restrict__ out) {
    int g = blockIdx.x;   // 64
    int t = threadIdx.x;  // 192
    __shared__ float pooled[192];
    __shared__ int sst, sen;
    if (t == 0) {
        int lo = 0, hi = NN;
        while (lo < hi) { int mid = (lo + hi) >> 1; if (batch[mid] < g) lo = mid + 1; else hi = mid; }
        sst = lo;
        hi = NN;
        while (lo < hi) { int mid = (lo + hi) >> 1; if (batch[mid] < g + 1) lo = mid + 1; else hi = mid; }
        sen = lo;
    }
    __syncthreads();
    float s = 0.f;
    for (int r = sst; r < sen; r++) s += g_h[(size_t)r * 192 + t];
    float c = (float)(sen - sst);
    pooled[t] = s / fmaxf(c, 1.0f);
    __syncthreads();
    if (t < 32) {
        float logit = 0.f, v = -1e30f;
        if (t < 10) {
            float acc = bf[t];
            for (int c2 = 0; c2 < 192; c2++) acc = fmaf(pooled[c2], Wf[c2 * 10 + t], acc);
            logit = acc; v = acc;
        }
#pragma unroll
        for (int o = 16; o; o >>= 1) v = fmaxf(v, __shfl_xor_sync(0xffffffffu, v, o));
        float e = (t < 10) ? __expf(logit - v) : 0.f;
        float sm = e;
#pragma unroll
        for (int o = 16; o; o >>= 1) sm += __shfl_xor_sync(0xffffffffu, sm, o);
        if (t < 10) out[g * 10 + t] = e / sm;
    }
}

// ---------------- launch --------------------------------------------------
extern "C" void kernel_launch(void* const* d_in, const int* in_sizes, int n_in,
                              void* d_out, int out_size) {
    const float* x     = (const float*)d_in[0];
    const float* adj   = (const float*)d_in[1];
    const int*   batch = (const int*)d_in[2];
    const float* W[3]   = {(const float*)d_in[3],  (const float*)d_in[9],  (const float*)d_in[15]};
    const float* b[3]   = {(const float*)d_in[4],  (const float*)d_in[10], (const float*)d_in[16]};
    const float* a1w[3] = {(const float*)d_in[5],  (const float*)d_in[11], (const float*)d_in[17]};
    const float* a1b[3] = {(const float*)d_in[6],  (const float*)d_in[12], (const float*)d_in[18]};
    const float* a2w[3] = {(const float*)d_in[7],  (const float*)d_in[13], (const float*)d_in[19]};
    const float* a2b[3] = {(const float*)d_in[8],  (const float*)d_in[14], (const float*)d_in[20]};
    const float* Wf = (const float*)d_in[21];
    const float* bf = (const float*)d_in[22];
    float* out = (float*)d_out;

    // layer 1 GEMM (blocks 0-127) overlapped with CSR build (blocks 128-639)
    fused_csr_gemm1<<<640, 256>>>(x, adj, W[0], b[0], a1w[0], a1b[0], a2w[0], a2b[0]);
    aggregate<<<NN, 256>>>(0, 0);

    gemm_k<<<128, 256>>>(0, W[1], b[1], a1w[1], a1b[1], a2w[1], a2b[1]);
    aggregate<<<NN, 256>>>(1, 64);

    gemm_k<<<128, 256>>>(1, W[2], b[2], a1w[2], a1b[2], a2w[2], a2b[2]);
    aggregate<<<NN, 256>>>(0, 128);

    pool_head<<<NGRAPH, 192>>>(batch, Wf, bf, out);
}